// round 16
// baseline (speedup 1.0000x reference)
#include <cuda_runtime.h>

#define FOCAL_K  0.075f   /* 0.3 * ALPHA(0.25) */
#define CRIT_PEN 50.0
#define LN2_F    0.69314718055994530942f
#define L2E_F    1.44269504088896340736f

// accumulators: [0]=sum(w*ce) [1]=sum(0.3*focal+0.4*pen)
//               [2..4]=count per class [5]=miss count
// zero at module load; last block resets after finalize (graph-replay safe).
__device__ double g_acc[6];
__device__ unsigned int g_done;

__device__ __forceinline__ void acsl_sample(
    float o0, float o1, float o2, int tt,
    const float4* s_lut,
    float& a_wce, float& a_mix, unsigned& a_cnt)
{
    // base-2 domain: b = o * log2(e); outputs ~ N(0,1) so no overflow
    float b0 = o0 * L2E_F;
    float b1 = o1 * L2E_F;
    float b2 = o2 * L2E_F;
    float e0 = exp2f(b0);
    float e1 = exp2f(b1);
    float e2 = exp2f(b2);
    float S  = e0 + e1 + e2;
    float lgS = __log2f(S);

    float bt = (tt == 0) ? b0 : ((tt == 1) ? b1 : b2);
    float d  = lgS - bt;
    float ce = d * LN2_F;
    float pt = exp2f(-d);                // == exp(-ce)
    float omp = 1.0f - pt;

    // argmax, first-max tie-break (matches jnp.argmax)
    float m01 = fmaxf(o0, o1);
    int pred = (o2 > m01) ? 2 : ((o1 > o0) ? 1 : 0);

    float4 lut = s_lut[tt * 3 + pred];   // {0.4*pen, w, inc_bits, -}

    a_wce = __fmaf_rn(lut.y, ce, a_wce);
    a_mix = __fmaf_rn(omp * omp, FOCAL_K * ce, a_mix) + lut.x;
    a_cnt += __float_as_uint(lut.z);     // packed: n0|n1|n2|miss 8-bit fields
}

#define SAMPLE4(F0, F1, F2, T) \
    do { \
        acsl_sample((F0).x, (F0).y, (F0).z, (T).x, s_lut, a_wce, a_mix, a_cnt); \
        acsl_sample((F0).w, (F1).x, (F1).y, (T).y, s_lut, a_wce, a_mix, a_cnt); \
        acsl_sample((F1).z, (F1).w, (F2).x, (T).z, s_lut, a_wce, a_mix, a_cnt); \
        acsl_sample((F2).y, (F2).z, (F2).w, (T).w, s_lut, a_wce, a_mix, a_cnt); \
    } while (0)

__global__ __launch_bounds__(256, 5)
void acsl_fused_kernel(const float* __restrict__ outputs,
                       const int* __restrict__ targets,
                       const float* __restrict__ cw,
                       const float* __restrict__ pm,
                       int nvec, int B,
                       float* __restrict__ out, double invB)
{
    __shared__ float4 s_lut[9];
    __shared__ double s_part[6][8];
    __shared__ int    s_last;

    int tid = threadIdx.x;
    if (tid < 9) {
        int t = tid / 3, p = tid % 3;
        unsigned inc = (1u << (t * 8)) | ((unsigned)((t == 2) & (p != 2)) << 24);
        s_lut[tid] = make_float4(0.4f * pm[tid], cw[t], __uint_as_float(inc), 0.f);
    }
    __syncthreads();

    float a_wce = 0.f, a_mix = 0.f;
    unsigned a_cnt = 0u;

    int gthreads = gridDim.x * blockDim.x;
    int g = blockIdx.x * blockDim.x + tid;

    const float4* p4  = (const float4*)outputs + 3 * (size_t)g;
    const int4*   pt4 = (const int4*)targets + g;
    long pstride = 3 * (long)gthreads;

    // number of vec4 iterations this thread owns
    int ni = (g < nvec) ? ((nvec - g + gthreads - 1) / gthreads) : 0;

    // software-pipelined on OUTPUTS only: loads for iteration k+1 are issued
    // before computing iteration k; targets loaded just-in-time (their latency
    // hides under the pipelined outputs' compute phase).
    if (ni > 0) {
        float4 A0 = p4[0], A1 = p4[1], A2 = p4[2];
        p4 += pstride;

        float4 B0, B1, B2;
        int k = 0;
        while (true) {
            bool more = (k + 1 < ni);
            if (more) {
                B0 = p4[0]; B1 = p4[1]; B2 = p4[2];
                p4 += pstride;
            }
            {
                int4 At = *pt4; pt4 += gthreads;
                SAMPLE4(A0, A1, A2, At);
            }
            k++;
            if (!more) break;

            bool more2 = (k + 1 < ni);
            if (more2) {
                A0 = p4[0]; A1 = p4[1]; A2 = p4[2];
                p4 += pstride;
            }
            {
                int4 Bt = *pt4; pt4 += gthreads;
                SAMPLE4(B0, B1, B2, Bt);
            }
            k++;
            if (!more2) break;
        }
    }

    // scalar tail (empty when B % 4 == 0; kept for generality)
    int tail_start = nvec * 4;
    for (int i = tail_start + g; i < B; i += gthreads) {
        float o0 = outputs[3 * i], o1 = outputs[3 * i + 1], o2 = outputs[3 * i + 2];
        acsl_sample(o0, o1, o2, targets[i], s_lut, a_wce, a_mix, a_cnt);
    }

    // unpack counts before reduction (8-bit fields hold <=~64 samples/thread)
    int n0 = (int)( a_cnt        & 0xffu);
    int n1 = (int)((a_cnt >>  8) & 0xffu);
    int n2 = (int)((a_cnt >> 16) & 0xffu);
    int nm = (int)( a_cnt >> 24);

    #pragma unroll
    for (int off = 16; off > 0; off >>= 1) {
        a_wce += __shfl_xor_sync(0xffffffffu, a_wce, off);
        a_mix += __shfl_xor_sync(0xffffffffu, a_mix, off);
        n0    += __shfl_xor_sync(0xffffffffu, n0,    off);
        n1    += __shfl_xor_sync(0xffffffffu, n1,    off);
        n2    += __shfl_xor_sync(0xffffffffu, n2,    off);
        nm    += __shfl_xor_sync(0xffffffffu, nm,    off);
    }

    int wid = tid >> 5;
    int lid = tid & 31;
    if (lid == 0) {
        s_part[0][wid] = (double)a_wce;
        s_part[1][wid] = (double)a_mix;
        s_part[2][wid] = (double)n0;
        s_part[3][wid] = (double)n1;
        s_part[4][wid] = (double)n2;
        s_part[5][wid] = (double)nm;
    }
    __syncthreads();

    if (tid < 6) {
        double s = 0.0;
        #pragma unroll
        for (int w = 0; w < 8; w++) s += s_part[tid][w];
        atomicAdd(&g_acc[tid], s);
    }

    // last-block finalize
    __threadfence();
    if (tid == 0) {
        unsigned int prev = atomicAdd(&g_done, 1u);
        s_last = (prev == gridDim.x - 1u) ? 1 : 0;
    }
    __syncthreads();

    if (s_last && tid == 0) {
        volatile double* acc = g_acc;
        double wce = acc[0];
        double mix = acc[1] * invB;
        double m0 = acc[2], m1 = acc[3], m2 = acc[4];
        double miss = acc[5];
        double w0 = (double)cw[0], w1 = (double)cw[1], w2 = (double)cw[2];

        double sum_w = w0 * m0 + w1 * m1 + w2 * m2;
        double ce_loss = wce / sum_w;
        double crit = (m2 > 0.0) ? (miss / fmax(m2, 1.0)) * CRIT_PEN : 0.0;
        out[0] = (float)(ce_loss + mix + 0.6 * crit);

        #pragma unroll
        for (int i = 0; i < 6; i++) g_acc[i] = 0.0;
        __threadfence();
        g_done = 0u;
    }
}

extern "C" void kernel_launch(void* const* d_in, const int* in_sizes, int n_in,
                              void* d_out, int out_size)
{
    const float* outputs = (const float*)d_in[0];
    const int*   targets = (const int*)d_in[1];
    const float* cw      = (const float*)d_in[2];
    const float* pm      = (const float*)d_in[3];
    float* out = (float*)d_out;

    int B = in_sizes[1];
    int nvec = B / 4;

    int threads = 256;
    int blocks = 148 * 5;   // single full wave at 5 CTAs/SM (51-reg budget)
    int need = (nvec + threads - 1) / threads;
    if (blocks > need) blocks = need;
    if (blocks < 1) blocks = 1;

    acsl_fused_kernel<<<blocks, threads>>>(outputs, targets, cw, pm,
                                           nvec, B, out, 1.0 / (double)B);
}

// round 17
// speedup vs baseline: 1.1129x; 1.1129x over previous
#include <cuda_runtime.h>

#define FOCAL_K  0.075f   /* 0.3 * ALPHA(0.25) */
#define CRIT_PEN 50.0
#define LN2_F    0.69314718055994530942f
#define L2E_F    1.44269504088896340736f

// accumulators: [0]=sum(w*ce) [1]=sum(0.3*focal+0.4*pen)
//               [2..4]=count per class [5]=miss count
// zero at module load; last block resets after finalize (graph-replay safe).
__device__ double g_acc[6];
__device__ unsigned int g_done;

__device__ __forceinline__ void acsl_sample(
    float o0, float o1, float o2, int tt,
    const float4* s_lut,
    float& a_wce, float& a_mix, unsigned& a_cnt)
{
    // base-2 domain: b = o * log2(e); outputs ~ N(0,1) so no overflow
    float b0 = o0 * L2E_F;
    float b1 = o1 * L2E_F;
    float b2 = o2 * L2E_F;
    float e0 = exp2f(b0);
    float e1 = exp2f(b1);
    float e2 = exp2f(b2);
    float S  = e0 + e1 + e2;
    float lgS = __log2f(S);

    float bt = (tt == 0) ? b0 : ((tt == 1) ? b1 : b2);
    float d  = lgS - bt;
    float ce = d * LN2_F;
    float pt = exp2f(-d);                // == exp(-ce)
    float omp = 1.0f - pt;

    // argmax, first-max tie-break (matches jnp.argmax)
    float m01 = fmaxf(o0, o1);
    int pred = (o2 > m01) ? 2 : ((o1 > o0) ? 1 : 0);

    float4 lut = s_lut[tt * 3 + pred];   // {0.4*pen, w, inc_bits, -}

    a_wce = __fmaf_rn(lut.y, ce, a_wce);
    a_mix = __fmaf_rn(omp * omp, FOCAL_K * ce, a_mix) + lut.x;
    a_cnt += __float_as_uint(lut.z);     // packed: n0|n1|n2|miss 8-bit fields
}

#define SAMPLE4(F0, F1, F2, T) \
    do { \
        acsl_sample((F0).x, (F0).y, (F0).z, (T).x, s_lut, a_wce, a_mix, a_cnt); \
        acsl_sample((F0).w, (F1).x, (F1).y, (T).y, s_lut, a_wce, a_mix, a_cnt); \
        acsl_sample((F1).z, (F1).w, (F2).x, (T).z, s_lut, a_wce, a_mix, a_cnt); \
        acsl_sample((F2).y, (F2).z, (F2).w, (T).w, s_lut, a_wce, a_mix, a_cnt); \
    } while (0)

__global__ __launch_bounds__(256, 4)
void acsl_fused_kernel(const float* __restrict__ outputs,
                       const int* __restrict__ targets,
                       const float* __restrict__ cw,
                       const float* __restrict__ pm,
                       int nvec, int B,
                       float* __restrict__ out, double invB)
{
    __shared__ float4 s_lut[9];
    __shared__ double s_part[6][8];
    __shared__ int    s_last;

    int tid = threadIdx.x;
    if (tid < 9) {
        int t = tid / 3, p = tid % 3;
        unsigned inc = (1u << (t * 8)) | ((unsigned)((t == 2) & (p != 2)) << 24);
        s_lut[tid] = make_float4(0.4f * pm[tid], cw[t], __uint_as_float(inc), 0.f);
    }
    __syncthreads();

    float a_wce = 0.f, a_mix = 0.f;
    unsigned a_cnt = 0u;

    int gthreads = gridDim.x * blockDim.x;
    int g = blockIdx.x * blockDim.x + tid;

    const float4* p4  = (const float4*)outputs + 3 * (size_t)g;
    const int4*   pt4 = (const int4*)targets + g;
    long pstride = 3 * (long)gthreads;

    // number of vec4 iterations this thread owns
    int ni = (g < nvec) ? ((nvec - g + gthreads - 1) / gthreads) : 0;

    // software-pipelined: the FULL batch (outputs + targets) for iteration k+1
    // is issued before computing iteration k
    if (ni > 0) {
        float4 A0 = p4[0], A1 = p4[1], A2 = p4[2];
        int4   At = *pt4;
        p4 += pstride; pt4 += gthreads;

        float4 B0, B1, B2; int4 Bt;
        int k = 0;
        while (true) {
            bool more = (k + 1 < ni);
            if (more) {
                B0 = p4[0]; B1 = p4[1]; B2 = p4[2]; Bt = *pt4;
                p4 += pstride; pt4 += gthreads;
            }
            SAMPLE4(A0, A1, A2, At);
            k++;
            if (!more) break;

            bool more2 = (k + 1 < ni);
            if (more2) {
                A0 = p4[0]; A1 = p4[1]; A2 = p4[2]; At = *pt4;
                p4 += pstride; pt4 += gthreads;
            }
            SAMPLE4(B0, B1, B2, Bt);
            k++;
            if (!more2) break;
        }
    }

    // scalar tail (empty when B % 4 == 0; kept for generality)
    int tail_start = nvec * 4;
    for (int i = tail_start + g; i < B; i += gthreads) {
        float o0 = outputs[3 * i], o1 = outputs[3 * i + 1], o2 = outputs[3 * i + 2];
        acsl_sample(o0, o1, o2, targets[i], s_lut, a_wce, a_mix, a_cnt);
    }

    // unpack counts before reduction (8-bit fields hold <=~64 samples/thread)
    int n0 = (int)( a_cnt        & 0xffu);
    int n1 = (int)((a_cnt >>  8) & 0xffu);
    int n2 = (int)((a_cnt >> 16) & 0xffu);
    int nm = (int)( a_cnt >> 24);

    #pragma unroll
    for (int off = 16; off > 0; off >>= 1) {
        a_wce += __shfl_xor_sync(0xffffffffu, a_wce, off);
        a_mix += __shfl_xor_sync(0xffffffffu, a_mix, off);
        n0    += __shfl_xor_sync(0xffffffffu, n0,    off);
        n1    += __shfl_xor_sync(0xffffffffu, n1,    off);
        n2    += __shfl_xor_sync(0xffffffffu, n2,    off);
        nm    += __shfl_xor_sync(0xffffffffu, nm,    off);
    }

    int wid = tid >> 5;
    int lid = tid & 31;
    if (lid == 0) {
        s_part[0][wid] = (double)a_wce;
        s_part[1][wid] = (double)a_mix;
        s_part[2][wid] = (double)n0;
        s_part[3][wid] = (double)n1;
        s_part[4][wid] = (double)n2;
        s_part[5][wid] = (double)nm;
    }
    __syncthreads();

    if (tid < 6) {
        double s = 0.0;
        #pragma unroll
        for (int w = 0; w < 8; w++) s += s_part[tid][w];
        atomicAdd(&g_acc[tid], s);
    }

    // last-block finalize
    __threadfence();
    if (tid == 0) {
        unsigned int prev = atomicAdd(&g_done, 1u);
        s_last = (prev == gridDim.x - 1u) ? 1 : 0;
    }
    __syncthreads();

    if (s_last && tid == 0) {
        volatile double* acc = g_acc;
        double wce = acc[0];
        double mix = acc[1] * invB;
        double m0 = acc[2], m1 = acc[3], m2 = acc[4];
        double miss = acc[5];
        double w0 = (double)cw[0], w1 = (double)cw[1], w2 = (double)cw[2];

        double sum_w = w0 * m0 + w1 * m1 + w2 * m2;
        double ce_loss = wce / sum_w;
        double crit = (m2 > 0.0) ? (miss / fmax(m2, 1.0)) * CRIT_PEN : 0.0;
        out[0] = (float)(ce_loss + mix + 0.6 * crit);

        #pragma unroll
        for (int i = 0; i < 6; i++) g_acc[i] = 0.0;
        __threadfence();
        g_done = 0u;
    }
}

extern "C" void kernel_launch(void* const* d_in, const int* in_sizes, int n_in,
                              void* d_out, int out_size)
{
    const float* outputs = (const float*)d_in[0];
    const int*   targets = (const int*)d_in[1];
    const float* cw      = (const float*)d_in[2];
    const float* pm      = (const float*)d_in[3];
    float* out = (float*)d_out;

    int B = in_sizes[1];
    int nvec = B / 4;

    int threads = 256;
    int blocks = 148 * 4;   // single full wave at 4 CTAs/SM (64-reg budget)
    int need = (nvec + threads - 1) / threads;
    if (blocks > need) blocks = need;
    if (blocks < 1) blocks = 1;

    acsl_fused_kernel<<<blocks, threads>>>(outputs, targets, cw, pm,
                                           nvec, B, out, 1.0 / (double)B);
}